// round 7
// baseline (speedup 1.0000x reference)
#include <cuda_runtime.h>
#include <cuda_bf16.h>
#include <cstdint>

// Problem constants
#define T_STEPS 500
#define B_SZ    128
#define K_SZ    256
#define F_SZ    512
#define C_SZ    10
#define MROWS   (T_STEPS * B_SZ)   // 64000
#define NEURONS (B_SZ * F_SZ)      // 65536

// ---- Hybrid GEMM: HMMA blocks cover cols 0-287, FFMA blocks cover 288-511 ----
// HMMA: TM=128, TN=96, KC=32 (8 chunks), 8 warps of 32x48, 3-term bf16.
// FFMA: 64x112 tiles, fp32 exact, thread tile 4m x 7n, f32x2 packed.
#define PITCH_H 80                  // 32 bf16 = 64B data + 16B pad
#define H_AHI 0
#define H_ALO 10240                 // 128*80
#define H_BHI 20480
#define H_BLO 28160                 // +96*80
#define STAGE_H 35840
#define SMEM_TOTAL (2 * STAGE_H)    // 71680 B per block; 2 blocks/SM

// FFMA smem layout (within same allocation): A [64][36]f at FA(s), B-T [32][116]f at FB(s)
#define FA(s) ((s) * 9216)
#define FB(s) (18432 + (s) * 14848)

#define NB 3500                     // 500*7: per q7: 3 HMMA (nt 0..2) + 4 FFMA (2 m-halves x 2 ntiles)

// Scratch
__device__ float g_proj[MROWS * F_SZ];            // 131 MB
__device__ float g_counts[NEURONS];
__device__ __nv_bfloat16 g_xhi[MROWS * K_SZ];
__device__ __nv_bfloat16 g_xlo[MROWS * K_SZ];
__device__ __nv_bfloat16 g_whi[F_SZ * K_SZ];
__device__ __nv_bfloat16 g_wlo[F_SZ * K_SZ];

// ---------------- helpers ----------------
__device__ __forceinline__ uint32_t smem_u32(const void* p) {
    uint32_t a;
    asm("{ .reg .u64 t; cvta.to.shared.u64 t, %1; cvt.u32.u64 %0, t; }" : "=r"(a) : "l"(p));
    return a;
}
__device__ __forceinline__ void cp_async16(uint32_t dst, const void* src) {
    asm volatile("cp.async.cg.shared.global [%0], [%1], 16;" :: "r"(dst), "l"(src) : "memory");
}
#define CP_COMMIT() asm volatile("cp.async.commit_group;" ::: "memory")

__device__ __forceinline__ void ldmx4(uint32_t* r, uint32_t addr) {
    asm volatile("ldmatrix.sync.aligned.m8n8.x4.shared.b16 {%0,%1,%2,%3}, [%4];"
                 : "=r"(r[0]), "=r"(r[1]), "=r"(r[2]), "=r"(r[3]) : "r"(addr));
}
__device__ __forceinline__ void mma_bf16(float* c, const uint32_t* a, const uint32_t* b) {
    asm volatile(
        "mma.sync.aligned.m16n8k16.row.col.f32.bf16.bf16.f32 "
        "{%0,%1,%2,%3}, {%4,%5,%6,%7}, {%8,%9}, {%0,%1,%2,%3};"
        : "+f"(c[0]), "+f"(c[1]), "+f"(c[2]), "+f"(c[3])
        : "r"(a[0]), "r"(a[1]), "r"(a[2]), "r"(a[3]), "r"(b[0]), "r"(b[1]));
}
__device__ __forceinline__ unsigned long long pack2(float lo, float hi) {
    unsigned long long d;
    asm("mov.b64 %0, {%1, %2};" : "=l"(d) : "r"(__float_as_uint(lo)), "r"(__float_as_uint(hi)));
    return d;
}
__device__ __forceinline__ void fma2(unsigned long long& d, unsigned long long a, unsigned long long b) {
    asm("fma.rn.f32x2 %0, %1, %2, %0;" : "+l"(d) : "l"(a), "l"(b));
}
__device__ __forceinline__ void unpack2(unsigned long long v, float& lo, float& hi) {
    unsigned int a, b;
    asm("mov.b64 {%0, %1}, %2;" : "=r"(a), "=r"(b) : "l"(v));
    lo = __uint_as_float(a); hi = __uint_as_float(b);
}

// ---------------- Pass 0: fp32 -> bf16 hi/lo split ----------------
__global__ void convert_split_kernel(const float4* __restrict__ xsrc, int nx4,
                                     const float4* __restrict__ wsrc, int nw4,
                                     uint2* __restrict__ xhi, uint2* __restrict__ xlo,
                                     uint2* __restrict__ whi, uint2* __restrict__ wlo)
{
    int i = blockIdx.x * blockDim.x + threadIdx.x;
    const float4* src; uint2* hi; uint2* lo; int idx;
    if (i < nx4)            { src = xsrc; hi = xhi; lo = xlo; idx = i; }
    else if (i < nx4 + nw4) { src = wsrc; hi = whi; lo = wlo; idx = i - nx4; }
    else return;
    float4 v = src[idx];
    __nv_bfloat16 h0 = __float2bfloat16(v.x), h1 = __float2bfloat16(v.y);
    __nv_bfloat16 h2 = __float2bfloat16(v.z), h3 = __float2bfloat16(v.w);
    __nv_bfloat16 l0 = __float2bfloat16(v.x - __bfloat162float(h0));
    __nv_bfloat16 l1 = __float2bfloat16(v.y - __bfloat162float(h1));
    __nv_bfloat16 l2 = __float2bfloat16(v.z - __bfloat162float(h2));
    __nv_bfloat16 l3 = __float2bfloat16(v.w - __bfloat162float(h3));
    uint2 ph, pl;
    ph.x = (uint32_t)*(uint16_t*)&h0 | ((uint32_t)*(uint16_t*)&h1 << 16);
    ph.y = (uint32_t)*(uint16_t*)&h2 | ((uint32_t)*(uint16_t*)&h3 << 16);
    pl.x = (uint32_t)*(uint16_t*)&l0 | ((uint32_t)*(uint16_t*)&l1 << 16);
    pl.y = (uint32_t)*(uint16_t*)&l2 | ((uint32_t)*(uint16_t*)&l3 << 16);
    hi[idx] = ph;
    lo[idx] = pl;
}

// ---------------- Pass 1: hybrid GEMM ----------------
__global__ __launch_bounds__(256, 2)
void snn_gemm_hybrid(const float* __restrict__ x,     // [64000, 256] fp32
                     const float* __restrict__ wts)   // [512, 256] fp32
{
    extern __shared__ char smem[];
    const uint32_t sb = smem_u32(smem);
    const int tid  = threadIdx.x;
    const int bid  = blockIdx.x;
    const int q7   = bid / 7;       // 0..499
    const int r7   = bid % 7;

    if (r7 < 3) {
        // ================= HMMA block: rows q7*128, cols r7*96 =================
        const int mt = q7, nt = r7;
        const int lane = tid & 31;
        const int wid  = tid >> 5;
        const int wm   = wid >> 1;      // 0..3 -> 32-row block
        const int wn   = wid & 1;       // 0..1 -> 48-col block
        const uint32_t laneoff = (uint32_t)((lane & 15) * PITCH_H + (lane >> 4) * 16);

        float acc[2][6][4];
        #pragma unroll
        for (int mi = 0; mi < 2; ++mi)
            #pragma unroll
            for (int ni = 0; ni < 6; ++ni)
                #pragma unroll
                for (int q = 0; q < 4; ++q) acc[mi][ni][q] = 0.f;

        // stage chunk c into buffer s
        auto stage = [&](int s, int c) {
            const uint32_t base = sb + s * STAGE_H;
            #pragma unroll
            for (int i = 0; i < 2; ++i) {           // A: 128 rows x 4 segs = 512
                int v = tid + 256 * i;
                int row = v >> 2, seg = v & 3;
                uint32_t d = base + row * PITCH_H + seg * 16;
                size_t o = (size_t)(mt * 128 + row) * K_SZ + c * 32 + seg * 8;
                cp_async16(d + H_AHI, g_xhi + o);
                cp_async16(d + H_ALO, g_xlo + o);
            }
            #pragma unroll
            for (int i = 0; i < 2; ++i) {           // B: 96 rows x 4 segs = 384
                int v = tid + 256 * i;
                if (v < 384) {
                    int row = v >> 2, seg = v & 3;
                    uint32_t d = base + row * PITCH_H + seg * 16;
                    size_t o = (size_t)(nt * 96 + row) * K_SZ + c * 32 + seg * 8;
                    cp_async16(d + H_BHI, g_whi + o);
                    cp_async16(d + H_BLO, g_wlo + o);
                }
            }
        };

        stage(0, 0);
        CP_COMMIT();

        for (int c = 0; c < 8; ++c) {
            const int s = c & 1;
            if (c < 7) {
                stage(s ^ 1, c + 1);
                CP_COMMIT();
                asm volatile("cp.async.wait_group 1;" ::: "memory");
            } else {
                asm volatile("cp.async.wait_group 0;" ::: "memory");
            }
            __syncthreads();

            const uint32_t base = sb + s * STAGE_H;
            #pragma unroll
            for (int kk = 0; kk < 2; ++kk) {
                uint32_t ah[2][4], al[2][4];
                #pragma unroll
                for (int mi = 0; mi < 2; ++mi) {
                    uint32_t addr = base + (uint32_t)((wm * 32 + mi * 16) * PITCH_H + kk * 32) + laneoff;
                    ldmx4(ah[mi], addr + H_AHI);
                    ldmx4(al[mi], addr + H_ALO);
                }
                uint32_t bh[6][2], bl[6][2];
                #pragma unroll
                for (int p = 0; p < 3; ++p) {
                    uint32_t addr = base + (uint32_t)((wn * 48 + p * 16) * PITCH_H + kk * 32) + laneoff;
                    uint32_t r[4];
                    ldmx4(r, addr + H_BHI);
                    bh[2*p][0] = r[0]; bh[2*p][1] = r[2];
                    bh[2*p+1][0] = r[1]; bh[2*p+1][1] = r[3];
                    ldmx4(r, addr + H_BLO);
                    bl[2*p][0] = r[0]; bl[2*p][1] = r[2];
                    bl[2*p+1][0] = r[1]; bl[2*p+1][1] = r[3];
                }
                #pragma unroll
                for (int mi = 0; mi < 2; ++mi)
                    #pragma unroll
                    for (int ni = 0; ni < 6; ++ni) {
                        mma_bf16(acc[mi][ni], ah[mi], bh[ni]);
                        mma_bf16(acc[mi][ni], ah[mi], bl[ni]);
                        mma_bf16(acc[mi][ni], al[mi], bh[ni]);
                    }
            }
            __syncthreads();
        }

        // Epilogue
        const int g  = lane >> 2;
        const int tg = lane & 3;
        #pragma unroll
        for (int mi = 0; mi < 2; ++mi) {
            const int m0 = mt * 128 + wm * 32 + mi * 16 + g;
            #pragma unroll
            for (int ni = 0; ni < 6; ++ni) {
                const int nc = nt * 96 + wn * 48 + ni * 8 + tg * 2;
                *reinterpret_cast<float2*>(&g_proj[(size_t)m0 * F_SZ + nc]) =
                    make_float2(acc[mi][ni][0], acc[mi][ni][1]);
                *reinterpret_cast<float2*>(&g_proj[(size_t)(m0 + 8) * F_SZ + nc]) =
                    make_float2(acc[mi][ni][2], acc[mi][ni][3]);
            }
        }
    } else {
        // ================= FFMA block: rows (q7*2+half)*64, cols 288 + fnt*112 =================
        const int sub = r7 - 3;               // 0..3
        const int fm  = q7 * 2 + (sub >> 1);  // 0..999
        const int fnt = sub & 1;
        const int m0b = fm * 64;
        const int n0b = 288 + fnt * 112;
        const int ng  = tid & 15;             // n0 = 7*ng
        const int mg  = tid >> 4;             // m0 = 4*mg
        const int n0  = ng * 7;
        const int m0  = mg * 4;

        unsigned long long acc2[4][3];
        float acc1[4];
        #pragma unroll
        for (int i = 0; i < 4; ++i) {
            acc1[i] = 0.f;
            #pragma unroll
            for (int j = 0; j < 3; ++j) acc2[i][j] = 0ULL;
        }

        auto stageA = [&](int s, int c) {
            #pragma unroll
            for (int i = 0; i < 2; ++i) {        // 64 rows x 8 segs = 512
                int v = tid + 256 * i;
                int row = v >> 3, seg = v & 7;
                cp_async16(sb + FA(s) + row * 144 + seg * 16,
                           x + (size_t)(m0b + row) * K_SZ + c * 32 + seg * 4);
            }
        };
        float4 bv[4];
        auto ldgB = [&](int c, float4* r) {
            #pragma unroll
            for (int i = 0; i < 4; ++i) {        // 112 rows x 8 f4 = 896
                int v = tid + 256 * i;
                if (v < 896) {
                    int row = v >> 3, c4 = v & 7;
                    r[i] = *reinterpret_cast<const float4*>(
                        wts + (size_t)(n0b + row) * K_SZ + c * 32 + c4 * 4);
                }
            }
        };
        auto stsB = [&](int s, const float4* r) {
            #pragma unroll
            for (int i = 0; i < 4; ++i) {
                int v = tid + 256 * i;
                if (v < 896) {
                    int row = v >> 3, c4 = v & 7;
                    float* d = reinterpret_cast<float*>(smem + FB(s)) + row;
                    d[(c4 * 4 + 0) * 116] = r[i].x;
                    d[(c4 * 4 + 1) * 116] = r[i].y;
                    d[(c4 * 4 + 2) * 116] = r[i].z;
                    d[(c4 * 4 + 3) * 116] = r[i].w;
                }
            }
        };

        stageA(0, 0);
        CP_COMMIT();
        ldgB(0, bv);
        asm volatile("cp.async.wait_group 0;" ::: "memory");
        __syncthreads();
        stsB(0, bv);
        __syncthreads();

        for (int c = 0; c < 8; ++c) {
            const int s = c & 1;
            float4 nv[4];
            if (c < 7) {
                stageA(s ^ 1, c + 1);
                CP_COMMIT();
                ldgB(c + 1, nv);
            }

            const float* As = reinterpret_cast<const float*>(smem + FA(s));
            const float* Bs = reinterpret_cast<const float*>(smem + FB(s));
            #pragma unroll 8
            for (int k = 0; k < 32; ++k) {
                float xv[4];
                unsigned long long xp[4];
                #pragma unroll
                for (int i = 0; i < 4; ++i) {
                    xv[i] = As[(m0 + i) * 36 + k];
                    xp[i] = pack2(xv[i], xv[i]);
                }
                const float* wr = Bs + k * 116 + n0;
                float w0 = wr[0], w1 = wr[1], w2 = wr[2], w3 = wr[3];
                float w4 = wr[4], w5 = wr[5], w6 = wr[6];
                unsigned long long wp0 = pack2(w0, w1);
                unsigned long long wp1 = pack2(w2, w3);
                unsigned long long wp2 = pack2(w4, w5);
                #pragma unroll
                for (int i = 0; i < 4; ++i) {
                    fma2(acc2[i][0], xp[i], wp0);
                    fma2(acc2[i][1], xp[i], wp1);
                    fma2(acc2[i][2], xp[i], wp2);
                    acc1[i] = fmaf(xv[i], w6, acc1[i]);
                }
            }

            if (c < 7) {
                asm volatile("cp.async.wait_group 0;" ::: "memory");
                __syncthreads();
                stsB(s ^ 1, nv);
                __syncthreads();
            }
        }

        // Epilogue: 7 floats per m row
        #pragma unroll
        for (int i = 0; i < 4; ++i) {
            float* dst = g_proj + (size_t)(m0b + m0 + i) * F_SZ + n0b + n0;
            float a, b;
            unpack2(acc2[i][0], a, b); dst[0] = a; dst[1] = b;
            unpack2(acc2[i][1], a, b); dst[2] = a; dst[3] = b;
            unpack2(acc2[i][2], a, b); dst[4] = a; dst[5] = b;
            dst[6] = acc1[i];
        }
    }
}

// ---------------- Pass 2: LIF scan ----------------
__global__ __launch_bounds__(512, 1)
void snn_scan_kernel()
{
    const int n = blockIdx.x * 512 + threadIdx.x;   // 0..65535
    const float* p = g_proj + n;
    float u = 0.f, tr = 0.f, cnt = 0.f;
    #pragma unroll 1
    for (int t = 0; t < T_STEPS; t += 20) {         // 500 = 25 * 20, no guards
        float v[20];
        #pragma unroll
        for (int j = 0; j < 20; ++j)
            v[j] = __ldcs(p + (size_t)(t + j) * NEURONS);
        #pragma unroll
        for (int j = 0; j < 20; ++j) {
            tr = 0.95f * tr + v[j];
            u  = 0.90f * u + tr;
            if (u > 1.0f) { cnt += 1.0f; u = 0.0f; }
        }
    }
    g_counts[n] = cnt;
}

// ---------------- Pass 3: decoder ----------------
__global__ __launch_bounds__(320, 1)
void snn_decode_kernel(const float* __restrict__ dec_w,
                       const float* __restrict__ dec_b,
                       float* __restrict__ out)
{
    const int b = blockIdx.x;
    const int c = threadIdx.x >> 5;
    const int l = threadIdx.x & 31;
    const float* cnt = g_counts + (size_t)b * F_SZ;
    const float* dwr = dec_w + (size_t)c * F_SZ;
    float s = 0.f;
    #pragma unroll
    for (int fi = l; fi < F_SZ; fi += 32)
        s += cnt[fi] * dwr[fi];
    #pragma unroll
    for (int o = 16; o > 0; o >>= 1)
        s += __shfl_down_sync(0xffffffffu, s, o);
    if (l == 0)
        out[b * C_SZ + c] = s + dec_b[c];
}

extern "C" void kernel_launch(void* const* d_in, const int* in_sizes, int n_in,
                              void* d_out, int out_size)
{
    const float* x     = (const float*)d_in[0];
    const float* wts   = (const float*)d_in[1];
    const float* dec_w = (const float*)d_in[2];
    const float* dec_b = (const float*)d_in[3];
    float* out = (float*)d_out;

    static uint2* p_xhi = nullptr; static uint2* p_xlo = nullptr;
    static uint2* p_whi = nullptr; static uint2* p_wlo = nullptr;
    if (!p_xhi) {
        cudaGetSymbolAddress((void**)&p_xhi, g_xhi);
        cudaGetSymbolAddress((void**)&p_xlo, g_xlo);
        cudaGetSymbolAddress((void**)&p_whi, g_whi);
        cudaGetSymbolAddress((void**)&p_wlo, g_wlo);
        cudaFuncSetAttribute(snn_gemm_hybrid,
                             cudaFuncAttributeMaxDynamicSharedMemorySize, SMEM_TOTAL);
    }

    const int nx4 = MROWS * K_SZ / 4;
    const int nw4 = F_SZ * K_SZ / 4;
    convert_split_kernel<<<(nx4 + nw4 + 255) / 256, 256>>>(
        (const float4*)x, nx4, (const float4*)wts, nw4, p_xhi, p_xlo, p_whi, p_wlo);

    snn_gemm_hybrid<<<NB, 256, SMEM_TOTAL>>>(x, wts);
    snn_scan_kernel<<<NEURONS / 512, 512>>>();
    snn_decode_kernel<<<B_SZ, 320>>>(dec_w, dec_b, out);
}

// round 8
// speedup vs baseline: 1.5528x; 1.5528x over previous
#include <cuda_runtime.h>
#include <cuda_bf16.h>
#include <cstdint>

// Problem constants
#define T_STEPS 500
#define B_SZ    128
#define K_SZ    256
#define F_SZ    512
#define C_SZ    10
#define MROWS   (T_STEPS * B_SZ)   // 64000
#define NEURONS (B_SZ * F_SZ)      // 65536

// GEMM tiling (round-5 proven config): CTA 128x128, 8 warps of 64x32, KC=64.
#define TM 128
#define TN 128
#define KC 64
#define NCHUNK (K_SZ / KC)   // 4
#define GT 256

// Padded smem rows: 64 bf16 (128B) + 16B pad = 144 B
#define PITCHB     144
#define TILEBYTES  (128 * PITCHB)      // 18432
#define A_HI 0
#define A_LO TILEBYTES
#define B_HI (2 * TILEBYTES)
#define B_LO (3 * TILEBYTES)
#define STAGEBYTES (4 * TILEBYTES)     // 73728
#define SMEM_TOTAL (2 * STAGEBYTES)    // 147456

// Scratch: proj + counts + pre-split weights (x is split in-kernel now)
__device__ float g_proj[MROWS * F_SZ];            // 131 MB
__device__ float g_counts[NEURONS];
__device__ __nv_bfloat16 g_whi[F_SZ * K_SZ];
__device__ __nv_bfloat16 g_wlo[F_SZ * K_SZ];

// ---------------- helpers ----------------
__device__ __forceinline__ uint32_t smem_u32(const void* p) {
    uint32_t a;
    asm("{ .reg .u64 t; cvta.to.shared.u64 t, %1; cvt.u32.u64 %0, t; }" : "=r"(a) : "l"(p));
    return a;
}
__device__ __forceinline__ void cp_async16(uint32_t dst, const void* src) {
    asm volatile("cp.async.cg.shared.global [%0], [%1], 16;" :: "r"(dst), "l"(src) : "memory");
}
#define CP_COMMIT() asm volatile("cp.async.commit_group;" ::: "memory")

__device__ __forceinline__ void ldmx4(uint32_t* r, uint32_t addr) {
    asm volatile("ldmatrix.sync.aligned.m8n8.x4.shared.b16 {%0,%1,%2,%3}, [%4];"
                 : "=r"(r[0]), "=r"(r[1]), "=r"(r[2]), "=r"(r[3]) : "r"(addr));
}
__device__ __forceinline__ void mma_bf16(float* c, const uint32_t* a, const uint32_t* b) {
    asm volatile(
        "mma.sync.aligned.m16n8k16.row.col.f32.bf16.bf16.f32 "
        "{%0,%1,%2,%3}, {%4,%5,%6,%7}, {%8,%9}, {%0,%1,%2,%3};"
        : "+f"(c[0]), "+f"(c[1]), "+f"(c[2]), "+f"(c[3])
        : "r"(a[0]), "r"(a[1]), "r"(a[2]), "r"(a[3]), "r"(b[0]), "r"(b[1]));
}
// float2 -> packed (hi bf16 x2, lo bf16 x2)
__device__ __forceinline__ void split2(float a, float b, uint32_t& hi, uint32_t& lo) {
    __nv_bfloat16 h0 = __float2bfloat16(a), h1 = __float2bfloat16(b);
    __nv_bfloat16 l0 = __float2bfloat16(a - __bfloat162float(h0));
    __nv_bfloat16 l1 = __float2bfloat16(b - __bfloat162float(h1));
    hi = (uint32_t)*(uint16_t*)&h0 | ((uint32_t)*(uint16_t*)&h1 << 16);
    lo = (uint32_t)*(uint16_t*)&l0 | ((uint32_t)*(uint16_t*)&l1 << 16);
}

// ---------------- Pass 0: W fp32 -> bf16 hi/lo (tiny) ----------------
__global__ void convert_w_kernel(const float4* __restrict__ wsrc,
                                 uint2* __restrict__ whi, uint2* __restrict__ wlo, int n4)
{
    int i = blockIdx.x * blockDim.x + threadIdx.x;
    if (i >= n4) return;
    float4 v = wsrc[i];
    uint2 ph, pl;
    split2(v.x, v.y, ph.x, pl.x);
    split2(v.z, v.w, ph.y, pl.y);
    whi[i] = ph;
    wlo[i] = pl;
}

// ---------------- Pass 1: GEMM proj = x @ W^T (A split in-kernel) ----------------
__global__ __launch_bounds__(GT, 1)
void snn_gemm_kernel(const float* __restrict__ x)   // [64000, 256] fp32
{
    extern __shared__ char smem[];
    const uint32_t sb = smem_u32(smem);
    const int tid  = threadIdx.x;
    const int lane = tid & 31;
    const int wid  = tid >> 5;
    const int wm   = wid >> 2;      // 0..1 -> 64-row block
    const int wn   = wid & 3;       // 0..3 -> 32-col block
    const int mtile = blockIdx.x;   // 0..499
    const int ntile = blockIdx.y;   // 0..3

    const uint32_t laneoff = (uint32_t)((lane & 15) * PITCHB + (lane >> 4) * 16);

    float acc[4][4][4];
    #pragma unroll
    for (int mi = 0; mi < 4; ++mi)
        #pragma unroll
        for (int ni = 0; ni < 4; ++ni)
            #pragma unroll
            for (int q = 0; q < 4; ++q) acc[mi][ni][q] = 0.f;

    // B staging: 128 rows x 8 segs(16B) per array, 4 passes of 32 rows.
    const int br = tid >> 3;
    const int bu = tid & 7;
    auto stageB = [&](int s, int c) {
        #pragma unroll
        for (int pass = 0; pass < 4; ++pass) {
            const int row = pass * 32 + br;
            const uint32_t d = sb + s * STAGEBYTES + row * PITCHB + bu * 16;
            const size_t o = (size_t)(ntile * TN + row) * K_SZ + c * KC + bu * 8;
            cp_async16(d + B_HI, g_whi + o);
            cp_async16(d + B_LO, g_wlo + o);
        }
    };
    // A: 128 rows x 16 float4 = 2048 units; 8 per thread.
    auto ldgA = [&](int c, float4* r) {
        #pragma unroll
        for (int i = 0; i < 8; ++i) {
            int v = tid + 256 * i;
            int row = v >> 4, seg = v & 15;
            r[i] = *reinterpret_cast<const float4*>(
                x + (size_t)(mtile * TM + row) * K_SZ + c * KC + seg * 4);
        }
    };
    auto stsA = [&](int s, const float4* r) {
        #pragma unroll
        for (int i = 0; i < 8; ++i) {
            int v = tid + 256 * i;
            int row = v >> 4, seg = v & 15;
            uint2 ph, pl;
            split2(r[i].x, r[i].y, ph.x, pl.x);
            split2(r[i].z, r[i].w, ph.y, pl.y);
            char* d = smem + s * STAGEBYTES + row * PITCHB + seg * 8;
            *reinterpret_cast<uint2*>(d + A_HI) = ph;
            *reinterpret_cast<uint2*>(d + A_LO) = pl;
        }
    };

    // Prologue: chunk 0
    float4 ra[8];
    ldgA(0, ra);
    stageB(0, 0);
    CP_COMMIT();
    stsA(0, ra);

    for (int c = 0; c < NCHUNK; ++c) {
        const int s = c & 1;
        float4 rn[8];
        if (c + 1 < NCHUNK) {
            ldgA(c + 1, rn);                 // latency hides under compute(c)
            stageB(s ^ 1, c + 1);
            CP_COMMIT();
            asm volatile("cp.async.wait_group 1;" ::: "memory");
        } else {
            asm volatile("cp.async.wait_group 0;" ::: "memory");
        }
        __syncthreads();                     // A(c) STS + B(c) cp.async visible

        const uint32_t base = sb + s * STAGEBYTES;
        #pragma unroll
        for (int kk = 0; kk < 4; ++kk) {
            uint32_t ah[4][4], al[4][4];
            #pragma unroll
            for (int mi = 0; mi < 4; ++mi) {
                uint32_t addr = base + (uint32_t)((wm * 64 + mi * 16) * PITCHB + kk * 32) + laneoff;
                ldmx4(ah[mi], addr + A_HI);
                ldmx4(al[mi], addr + A_LO);
            }
            uint32_t bh[4][2], bl[4][2];
            #pragma unroll
            for (int p = 0; p < 2; ++p) {
                uint32_t addr = base + (uint32_t)((wn * 32 + p * 16) * PITCHB + kk * 32) + laneoff;
                uint32_t r[4];
                ldmx4(r, addr + B_HI);
                bh[2*p][0] = r[0]; bh[2*p][1] = r[2];
                bh[2*p+1][0] = r[1]; bh[2*p+1][1] = r[3];
                ldmx4(r, addr + B_LO);
                bl[2*p][0] = r[0]; bl[2*p][1] = r[2];
                bl[2*p+1][0] = r[1]; bl[2*p+1][1] = r[3];
            }
            #pragma unroll
            for (int mi = 0; mi < 4; ++mi)
                #pragma unroll
                for (int ni = 0; ni < 4; ++ni) {
                    mma_bf16(acc[mi][ni], ah[mi], bh[ni]);   // xh * wh
                    mma_bf16(acc[mi][ni], ah[mi], bl[ni]);   // xh * wl
                    mma_bf16(acc[mi][ni], al[mi], bh[ni]);   // xl * wh
                }
        }

        if (c + 1 < NCHUNK)
            stsA(s ^ 1, rn);                 // writes other buffer: no conflict with compute(c)
        __syncthreads();                     // compute(c)+stsA done before next overwrite
    }

    // Epilogue: fragment -> gmem (float2 stores)
    const int g  = lane >> 2;
    const int tg = lane & 3;
    #pragma unroll
    for (int mi = 0; mi < 4; ++mi) {
        const int m0 = mtile * TM + wm * 64 + mi * 16 + g;
        #pragma unroll
        for (int ni = 0; ni < 4; ++ni) {
            const int nc = ntile * TN + wn * 32 + ni * 8 + tg * 2;
            *reinterpret_cast<float2*>(&g_proj[(size_t)m0 * F_SZ + nc]) =
                make_float2(acc[mi][ni][0], acc[mi][ni][1]);
            *reinterpret_cast<float2*>(&g_proj[(size_t)(m0 + 8) * F_SZ + nc]) =
                make_float2(acc[mi][ni][2], acc[mi][ni][3]);
        }
    }
}

// ---------------- Pass 2: LIF scan (deep MLP: 25 loads in flight) ----------------
__global__ __launch_bounds__(512, 1)
void snn_scan_kernel()
{
    const int n = blockIdx.x * 512 + threadIdx.x;   // 0..65535
    const float* p = g_proj + n;
    float u = 0.f, tr = 0.f, cnt = 0.f;
    #pragma unroll 1
    for (int t = 0; t < T_STEPS; t += 25) {         // 500 = 20 * 25
        float v[25];
        #pragma unroll
        for (int j = 0; j < 25; ++j)
            v[j] = __ldcs(p + (size_t)(t + j) * NEURONS);
        #pragma unroll
        for (int j = 0; j < 25; ++j) {
            tr = 0.95f * tr + v[j];
            u  = 0.90f * u + tr;
            if (u > 1.0f) { cnt += 1.0f; u = 0.0f; }
        }
    }
    g_counts[n] = cnt;
}

// ---------------- Pass 3: decoder ----------------
__global__ __launch_bounds__(320, 1)
void snn_decode_kernel(const float* __restrict__ dec_w,
                       const float* __restrict__ dec_b,
                       float* __restrict__ out)
{
    const int b = blockIdx.x;
    const int c = threadIdx.x >> 5;
    const int l = threadIdx.x & 31;
    const float* cnt = g_counts + (size_t)b * F_SZ;
    const float* dwr = dec_w + (size_t)c * F_SZ;
    float s = 0.f;
    #pragma unroll
    for (int fi = l; fi < F_SZ; fi += 32)
        s += cnt[fi] * dwr[fi];
    #pragma unroll
    for (int o = 16; o > 0; o >>= 1)
        s += __shfl_down_sync(0xffffffffu, s, o);
    if (l == 0)
        out[b * C_SZ + c] = s + dec_b[c];
}

extern "C" void kernel_launch(void* const* d_in, const int* in_sizes, int n_in,
                              void* d_out, int out_size)
{
    const float* x     = (const float*)d_in[0];
    const float* wts   = (const float*)d_in[1];
    const float* dec_w = (const float*)d_in[2];
    const float* dec_b = (const float*)d_in[3];
    float* out = (float*)d_out;

    static uint2* p_whi = nullptr; static uint2* p_wlo = nullptr;
    if (!p_whi) {
        cudaGetSymbolAddress((void**)&p_whi, g_whi);
        cudaGetSymbolAddress((void**)&p_wlo, g_wlo);
        cudaFuncSetAttribute(snn_gemm_kernel,
                             cudaFuncAttributeMaxDynamicSharedMemorySize, SMEM_TOTAL);
    }

    const int nw4 = F_SZ * K_SZ / 4;    // 32768
    convert_w_kernel<<<(nw4 + 255) / 256, 256>>>((const float4*)wts, p_whi, p_wlo, nw4);

    dim3 grid(MROWS / TM, F_SZ / TN);   // (500, 4)
    snn_gemm_kernel<<<grid, GT, SMEM_TOTAL>>>(x);
    snn_scan_kernel<<<NEURONS / 512, 512>>>();
    snn_decode_kernel<<<B_SZ, 320>>>(dec_w, dec_b, out);
}